// round 15
// baseline (speedup 1.0000x reference)
#include <cuda_runtime.h>
#include <cuda_fp16.h>
#include <cstdint>
#include <cstddef>

#define NAT 131072
#define NBO 262144
#define NMO 4096
#define DHP 320
#define DEM 256

// ---------------- scratch (device globals; no allocation) ----------------
__device__ __align__(16) __half g_H0[(size_t)NBO * DHP];
__device__ __align__(16) __half g_Hb[(size_t)NBO * DHP];
__device__ __align__(16) __half g_Mv1[(size_t)NAT * DHP];
__device__ __align__(16) __half g_Mv2[(size_t)NAT * DHP];
__device__ float g_Z [(size_t)NMO * DHP];
__device__ float g_cnt[NMO];
__device__ float g_T [(size_t)NMO * DEM];
__device__ float g_bo[DHP];
__device__ __align__(16) __half g_Bh0[320 * 96];
__device__ __align__(16) __half g_Bh [320 * 320];
__device__ __align__(16) __half g_Bo [320 * 384];
__device__ __align__(16) __half g_B1 [256 * 320];
__device__ __align__(16) __half g_B2 [256 * 256];

// ---------------- PTX helpers ----------------
__device__ __forceinline__ uint32_t smem_u32(const void* p) {
    uint32_t a;
    asm("{ .reg .u64 t; cvta.to.shared.u64 t, %1; cvt.u32.u64 %0, t; }"
        : "=r"(a) : "l"(p));
    return a;
}
__device__ __forceinline__ void cpa16(uint32_t dst, const void* src) {
    asm volatile("cp.async.cg.shared.global [%0], [%1], 16;"
                 :: "r"(dst), "l"(src) : "memory");
}
__device__ __forceinline__ void cp_commit() {
    asm volatile("cp.async.commit_group;" ::: "memory");
}
template<int N>
__device__ __forceinline__ void cp_wait() {
    asm volatile("cp.async.wait_group %0;" :: "n"(N) : "memory");
}
__device__ __forceinline__ void ldsm4(uint32_t* r, uint32_t a) {
    asm volatile("ldmatrix.sync.aligned.m8n8.x4.shared.b16 {%0,%1,%2,%3}, [%4];"
                 : "=r"(r[0]), "=r"(r[1]), "=r"(r[2]), "=r"(r[3]) : "r"(a));
}
__device__ __forceinline__ void mma16816(float* c, const uint32_t* a, const uint32_t* b) {
    asm volatile(
        "mma.sync.aligned.m16n8k16.row.col.f32.f16.f16.f32 "
        "{%0,%1,%2,%3}, {%4,%5,%6,%7}, {%8,%9}, {%0,%1,%2,%3};"
        : "+f"(c[0]), "+f"(c[1]), "+f"(c[2]), "+f"(c[3])
        : "r"(a[0]), "r"(a[1]), "r"(a[2]), "r"(a[3]), "r"(b[0]), "r"(b[1]));
}
__device__ __forceinline__ void sts16(uint32_t a, uint32_t x, uint32_t y,
                                      uint32_t z, uint32_t w) {
    asm volatile("st.shared.v4.b32 [%0], {%1,%2,%3,%4};"
                 :: "r"(a), "r"(x), "r"(y), "r"(z), "r"(w) : "memory");
}
__device__ __forceinline__ void red2f(float* addr, float x, float y) {
    asm volatile("red.global.add.v2.f32 [%0], {%1,%2};"
                 :: "l"(addr), "f"(x), "f"(y) : "memory");
}
__device__ __forceinline__ void red4h(__half* addr, uint32_t p, uint32_t q) {
    asm volatile("red.global.add.noftz.v2.f16x2 [%0], {%1,%2};"
                 :: "l"(addr), "r"(p), "r"(q) : "memory");
}

// ---------------- weight prep (transpose + fp16 round) ----------------
__global__ void prep_bt_k(const float* __restrict__ W, __half* __restrict__ out,
                          int Ksrc, int Nsrc, int KP, int Nrows) {
    int idx = blockIdx.x * 256 + threadIdx.x;
    if (idx >= Nrows * KP) return;
    int n = idx / KP, k = idx - n * KP;
    float v = (k < Ksrc && n < Nsrc) ? W[(size_t)k * Nsrc + n] : 0.f;
    out[(size_t)n * KP + k] = __float2half_rn(v);
}

__global__ void pad_k(const float* __restrict__ in, float* __restrict__ out,
                      int IC, int OC) {
    int idx = blockIdx.x * blockDim.x + threadIdx.x;
    if (idx >= OC) return;
    out[idx] = (idx < IC) ? in[idx] : 0.f;
}

__global__ void count_k(const int* __restrict__ batch, float* __restrict__ cnt) {
    int a = blockIdx.x * blockDim.x + threadIdx.x;
    if (a < NAT) atomicAdd(&cnt[batch[a]], 1.f);
}

// ---------------- fused GEMM (BM=64, BN=N, fp16, 3-stage pipeline) --------
// AMODE: 0 plain(f32) ; 1 h0 concat-gather(V,E f32) ;
//        2 message: Mv(f16)[g[r]] - H(f16)[(r^1)] ;
//        5 message+relu: Mv(f16) - relu(H(f16)[(r^1)]) ;
//        3 wo concat: V(f32) | Mv(f16)
// EPI:   0 C=acc+aux_f[c] (f32) ; 1 C=relu(acc+aux_f[c]) (f32) ;
//        2 v=relu(acc+aux_h[r*N+c]); C(f16)=v; scatter f16 ;
//        3 C(f16)=acc; scatter relu(acc) f16 ;
//        4 v=relu(acc+aux_h[r*N+c]); scatter f16 only ;
//        5 v=relu(acc+aux_f[c])/cnt[sidx[r]]; scatter f32 only (cnt via C2)
template<int AMODE>
__device__ __forceinline__ void loadA8(const void* __restrict__ A1v,
                                       const void* __restrict__ A2v,
                                       long long row, int s, int k0,
                                       int KP, float* va) {
    if (AMODE == 0) {
        const float4* p = (const float4*)((const float*)A1v + row * KP + k0);
        float4 a = p[0], b = p[1];
        va[0]=a.x; va[1]=a.y; va[2]=a.z; va[3]=a.w;
        va[4]=b.x; va[5]=b.y; va[6]=b.z; va[7]=b.w;
    } else if (AMODE == 2 || AMODE == 5) {
        const uint4 mv = *(const uint4*)((const __half*)A1v + (size_t)s * DHP + k0);
        const uint4 hv = *(const uint4*)((const __half*)A2v +
                                         (size_t)(row ^ 1) * DHP + k0);
        const __half2* mp = (const __half2*)&mv;
        const __half2* hp = (const __half2*)&hv;
#pragma unroll
        for (int i = 0; i < 4; i++) {
            float2 m = __half22float2(mp[i]);
            float2 h = __half22float2(hp[i]);
            if (AMODE == 5) { h.x = fmaxf(h.x, 0.f); h.y = fmaxf(h.y, 0.f); }
            va[2*i]   = m.x - h.x;
            va[2*i+1] = m.y - h.y;
        }
    } else if (AMODE == 1) {
        const float* A1 = (const float*)A1v;
        const float* A2 = (const float*)A2v;
#pragma unroll
        for (int j = 0; j < 8; j++) {
            int k = k0 + j;
            va[j] = (k < 72) ? A1[(size_t)s * 72 + k]
                             : (k < 86 ? A2[row * 14 + (k - 72)] : 0.f);
        }
    } else { // AMODE 3
        const float* A1 = (const float*)A1v;
        const __half* A2 = (const __half*)A2v;
#pragma unroll
        for (int j = 0; j < 8; j++) {
            int k = k0 + j;
            va[j] = (k < 72) ? A1[row * 72 + k]
                             : (k < 372 ? __half2float(A2[row * DHP + (k - 72)])
                                        : 0.f);
        }
    }
}

__device__ __forceinline__ void storeA8(uint32_t ahi, const float* va) {
    uint32_t h[4];
#pragma unroll
    for (int j = 0; j < 4; j++) {
        __half2 hp;
        hp.x = __float2half_rn(va[2*j]);
        hp.y = __float2half_rn(va[2*j+1]);
        h[j] = *(uint32_t*)&hp;
    }
    sts16(ahi, h[0], h[1], h[2], h[3]);
}

template<int AMODE, int EPI, int BN>
__global__ void __launch_bounds__(256, 2)
gemm_f(const void* __restrict__ A1v, const void* __restrict__ A2v,
       const int* __restrict__ gidx,
       const __half* __restrict__ Bt, int KP,
       const void* __restrict__ auxv,
       const int* __restrict__ sidx, void* __restrict__ Sv,
       void* __restrict__ Cv, const float* __restrict__ C2, int N) {
    constexpr int NT = BN / 32;                 // n-tiles (8 cols) per warp
    constexpr int RS = 80;
    constexpr int ABUF = 64 * RS;
    constexpr int BBUF = BN * RS;
    constexpr int STG = ABUF + BBUF;            // [Ahi][Bhi] per stage, x3
    extern __shared__ __align__(16) char sm[];
    const uint32_t sbase = smem_u32(sm);

    const int tid = threadIdx.x;
    const int wid = tid >> 5, lane = tid & 31;
    const int wm = wid & 1, wn = wid >> 1;
    const long long bm = (long long)blockIdx.y * 64;
    const int nW = KP >> 5;

    const int arow = tid >> 2;                  // 0..63
    const int kh = (tid & 3) * 8;               // 0,8,16,24
    const long long grow = bm + arow;
    const int s = (AMODE == 1 || AMODE == 2 || AMODE == 5) ? gidx[grow] : 0;

    float acc[2][NT][4];
#pragma unroll
    for (int i = 0; i < 2; i++)
#pragma unroll
        for (int j = 0; j < NT; j++)
#pragma unroll
            for (int t = 0; t < 4; t++) acc[i][j][t] = 0.f;

    const int aRow = (lane & 7) + ((lane >> 3) & 1) * 8;
    const int aK   = (lane >> 4) * 8;
    const int bRow4 = (lane & 7) + ((lane >> 4) << 3);
    const int bK4   = ((lane >> 3) & 1) * 8;

    auto loadB = [&](int w, int stg) {
        const uint32_t bhi = sbase + stg * STG + ABUF;
        for (int idx = tid; idx < BN * 4; idx += 256) {
            int row = idx >> 2, sg = idx & 3;
            cpa16(bhi + row * RS + sg * 16,
                  Bt + (size_t)row * KP + w * 32 + sg * 8);
        }
    };

    // prologue: stages 0 and 1
    {
        float va[8];
        loadA8<AMODE>(A1v, A2v, grow, s, kh, KP, va);
        storeA8(sbase + arow * RS + kh * 2, va);
        loadB(0, 0);
        cp_commit();
        loadA8<AMODE>(A1v, A2v, grow, s, 32 + kh, KP, va);
        storeA8(sbase + STG + arow * RS + kh * 2, va);
        loadB(1, 1);
        cp_commit();
    }

    for (int w = 0; w < nW; ++w) {
        const int stg = w % 3;
        if (w + 1 < nW) cp_wait<1>(); else cp_wait<0>();
        __syncthreads();                        // single barrier per window
        float va[8];
        const bool pre = (w + 2 < nW);
        if (pre) {
            loadB(w + 2, (w + 2) % 3);          // stage (w-1)%3: safe post-sync
            cp_commit();
            loadA8<AMODE>(A1v, A2v, grow, s, (w + 2) * 32 + kh, KP, va);
        }
        const uint32_t as = sbase + stg * STG;
        const uint32_t bs = as + ABUF;
#pragma unroll
        for (int ks = 0; ks < 32; ks += 16) {
            uint32_t afh[2][4];
#pragma unroll
            for (int mt = 0; mt < 2; ++mt) {
                uint32_t ar = as + (wm * 32 + mt * 16 + aRow) * RS + (ks + aK) * 2;
                ldsm4(afh[mt], ar);
            }
#pragma unroll
            for (int ntp = 0; ntp < NT / 2; ++ntp) {
                uint32_t bh4[4];
                uint32_t br = bs + (wn * NT * 8 + ntp * 16 + bRow4) * RS + (ks + bK4) * 2;
                ldsm4(bh4, br);
#pragma unroll
                for (int mt = 0; mt < 2; ++mt)
#pragma unroll
                    for (int h = 0; h < 2; ++h)
                        mma16816(acc[mt][ntp*2 + h], afh[mt], bh4 + h*2);
            }
        }
        if (pre) {
            storeA8(sbase + ((w + 2) % 3) * STG + arow * RS + kh * 2, va);
        }
    }

    // ---- epilogue ----
    const __half* auxh = (const __half*)auxv;
    const float*  auxf = (const float*)auxv;
    __half* Ch = (__half*)Cv;
    float*  Cf = (float*)Cv;
    __half* Sh = (__half*)Sv;
    float*  Sf = (float*)Sv;
    const int gid = lane >> 2, tig = lane & 3;
#pragma unroll
    for (int mt = 0; mt < 2; ++mt) {
        const long long r0 = bm + wm * 32 + mt * 16 + gid;
        const long long r1 = r0 + 8;
        int si0 = 0, si1 = 0;
        float inv0 = 1.f, inv1 = 1.f;
        if (EPI >= 2) { si0 = sidx[r0]; si1 = sidx[r1]; }
        if (EPI == 5) {
            inv0 = 1.f / fmaxf(C2[si0], 1.f);
            inv1 = 1.f / fmaxf(C2[si1], 1.f);
        }
#pragma unroll
        for (int nt = 0; nt < NT; ++nt) {
            const int c0 = wn * NT * 8 + nt * 8 + tig * 2;
            float v00 = acc[mt][nt][0], v01 = acc[mt][nt][1];
            float v10 = acc[mt][nt][2], v11 = acc[mt][nt][3];
            float r00, r01, r10, r11;
            if (EPI == 0 || EPI == 1 || EPI == 5) {
                float2 ax = *(const float2*)(auxf + c0);
                r00 = v00 + ax.x; r01 = v01 + ax.y;
                r10 = v10 + ax.x; r11 = v11 + ax.y;
            } else if (EPI == 2 || EPI == 4) {
                float2 a0 = __half22float2(*(const __half2*)(auxh + r0 * N + c0));
                float2 a1 = __half22float2(*(const __half2*)(auxh + r1 * N + c0));
                r00 = v00 + a0.x; r01 = v01 + a0.y;
                r10 = v10 + a1.x; r11 = v11 + a1.y;
            } else { // EPI==3
                r00 = v00; r01 = v01; r10 = v10; r11 = v11;
            }
            if (EPI != 0) {
                r00 = fmaxf(r00, 0.f); r01 = fmaxf(r01, 0.f);
                r10 = fmaxf(r10, 0.f); r11 = fmaxf(r11, 0.f);
            }
            if (EPI == 5) {
                r00 *= inv0; r01 *= inv0; r10 *= inv1; r11 *= inv1;
            }
            if (EPI == 0 || EPI == 1) {
                *(float2*)(Cf + r0 * N + c0) = make_float2(r00, r01);
                *(float2*)(Cf + r1 * N + c0) = make_float2(r10, r11);
            } else if (EPI == 2) {
                *(__half2*)(Ch + r0 * N + c0) = __floats2half2_rn(r00, r01);
                *(__half2*)(Ch + r1 * N + c0) = __floats2half2_rn(r10, r11);
            } else if (EPI == 3) {
                *(__half2*)(Ch + r0 * N + c0) = __floats2half2_rn(v00, v01);
                *(__half2*)(Ch + r1 * N + c0) = __floats2half2_rn(v10, v11);
            }
            if (EPI == 5) {
                float* s0 = Sf + (size_t)si0 * DHP + c0;
                float* s1 = Sf + (size_t)si1 * DHP + c0;
                if (r00 != 0.f || r01 != 0.f) red2f(s0, r00, r01);
                if (r10 != 0.f || r11 != 0.f) red2f(s1, r10, r11);
            } else if (EPI >= 2) {
                // pair lanes (tig, tig^1) -> one v2.f16x2 red covering 4 cols
                __half2 h0 = __floats2half2_rn(r00, r01);
                __half2 h1 = __floats2half2_rn(r10, r11);
                uint32_t p0 = *(uint32_t*)&h0;
                uint32_t p1 = *(uint32_t*)&h1;
                uint32_t q0 = __shfl_xor_sync(0xffffffffu, p0, 1);
                uint32_t q1 = __shfl_xor_sync(0xffffffffu, p1, 1);
                if ((tig & 1) == 0) {
                    __half* s0 = Sh + (size_t)si0 * DHP + c0;
                    __half* s1 = Sh + (size_t)si1 * DHP + c0;
                    if (p0 | q0) red4h(s0, p0, q0);
                    if (p1 | q1) red4h(s1, p1, q1);
                }
            }
        }
    }
}

// ---------------- launcher ----------------
extern "C" void kernel_launch(void* const* d_in, const int* in_sizes, int n_in,
                              void* d_out, int out_size) {
    const float* V    = (const float*)d_in[0];
    const float* E    = (const float*)d_in[1];
    const int*   esrc = (const int*)d_in[2];
    const int*   edst = (const int*)d_in[3];
    const int*   batc = (const int*)d_in[5];
    int wi = 6;
    if (n_in >= 15 && in_sizes[6] == 1) wi = 7;
    const float* W_i = (const float*)d_in[wi + 0];
    const float* W_h = (const float*)d_in[wi + 1];
    const float* W_o = (const float*)d_in[wi + 2];
    const float* b_o = (const float*)d_in[wi + 3];
    const float* W1  = (const float*)d_in[wi + 4];
    const float* b1  = (const float*)d_in[wi + 5];
    const float* W2  = (const float*)d_in[wi + 6];
    const float* b2  = (const float*)d_in[wi + 7];
    float* out = (float*)d_out;

    float *Z, *cnt, *T, *bo;
    __half *H0, *Hb, *Mv1, *Mv2, *Bh0, *Bh, *Bo, *B1, *B2;
    cudaGetSymbolAddress((void**)&H0,  g_H0);
    cudaGetSymbolAddress((void**)&Hb,  g_Hb);
    cudaGetSymbolAddress((void**)&Mv1, g_Mv1);
    cudaGetSymbolAddress((void**)&Mv2, g_Mv2);
    cudaGetSymbolAddress((void**)&Z,   g_Z);
    cudaGetSymbolAddress((void**)&cnt, g_cnt);
    cudaGetSymbolAddress((void**)&T,   g_T);
    cudaGetSymbolAddress((void**)&bo,  g_bo);
    cudaGetSymbolAddress((void**)&Bh0, g_Bh0);
    cudaGetSymbolAddress((void**)&Bh,  g_Bh);
    cudaGetSymbolAddress((void**)&Bo,  g_Bo);
    cudaGetSymbolAddress((void**)&B1,  g_B1);
    cudaGetSymbolAddress((void**)&B2,  g_B2);

    const int SMF320 = 3 * (64 * 80 + 320 * 80);  // 92160 (3 stages)
    const int SMF256 = 3 * (64 * 80 + 256 * 80);  // 76800
    cudaFuncSetAttribute(gemm_f<1,3,320>, cudaFuncAttributeMaxDynamicSharedMemorySize, SMF320);
    cudaFuncSetAttribute(gemm_f<5,2,320>, cudaFuncAttributeMaxDynamicSharedMemorySize, SMF320);
    cudaFuncSetAttribute(gemm_f<2,4,320>, cudaFuncAttributeMaxDynamicSharedMemorySize, SMF320);
    cudaFuncSetAttribute(gemm_f<3,5,320>, cudaFuncAttributeMaxDynamicSharedMemorySize, SMF320);
    cudaFuncSetAttribute(gemm_f<0,1,256>, cudaFuncAttributeMaxDynamicSharedMemorySize, SMF256);
    cudaFuncSetAttribute(gemm_f<0,0,256>, cudaFuncAttributeMaxDynamicSharedMemorySize, SMF256);

    // weight prep (transpose + fp16)
    prep_bt_k<<<(320 * 96  + 255) / 256, 256>>>(W_i, Bh0, 86,  300, 96,  320);
    prep_bt_k<<<(320 * 320 + 255) / 256, 256>>>(W_h, Bh,  300, 300, 320, 320);
    prep_bt_k<<<(320 * 384 + 255) / 256, 256>>>(W_o, Bo,  372, 300, 384, 320);
    prep_bt_k<<<(256 * 320 + 255) / 256, 256>>>(W1,  B1,  300, 256, 320, 256);
    prep_bt_k<<<(256 * 256 + 255) / 256, 256>>>(W2,  B2,  256, 256, 256, 256);
    pad_k<<<2, 256>>>(b_o, bo, 300, DHP);

    const size_t MVB = (size_t)NAT * DHP * sizeof(__half);
    cudaMemsetAsync(cnt, 0, (size_t)NMO * sizeof(float));
    count_k<<<(NAT + 255) / 256, 256>>>(batc, cnt);
    cudaMemsetAsync(Mv1, 0, MVB);
    cudaMemsetAsync(Mv2, 0, MVB);
    cudaMemsetAsync(Z, 0, (size_t)NMO * DHP * sizeof(float));

    // 1. H0(f16) = concat(V[src],E)@W_i (pre-relu) ; scatter relu -> Mv1(f16)
    gemm_f<1,3,320><<<dim3(1, NBO / 64), 256, SMF320>>>(
        V, E, esrc, Bh0, 96, nullptr, edst, Mv1, H0, nullptr, DHP);

    // 2. iter1: Hb(f16) = relu(H0 + (Mv1[src]-relu(H0)[rev])@Wh) ; scatter -> Mv2
    gemm_f<5,2,320><<<dim3(1, NBO / 64), 256, SMF320>>>(
        Mv1, H0, esrc, Bh, 320, H0, edst, Mv2, Hb, nullptr, DHP);

    // 3. iter2: relu(H0 + (Mv2[src]-Hb[rev])@Wh) scattered -> Mv1 (no store)
    cudaMemsetAsync(Mv1, 0, MVB);
    gemm_f<2,4,320><<<dim3(1, NBO / 64), 256, SMF320>>>(
        Mv2, Hb, esrc, Bh, 320, H0, edst, Mv1, nullptr, nullptr, DHP);

    // 4. relu(concat(V,Mv1)@Wo + bo) / cnt pooled -> Z(f32) (mean fused)
    gemm_f<3,5,320><<<dim3(1, NAT / 64), 256, SMF320>>>(
        V, Mv1, nullptr, Bo, 384, bo, batc, Z, nullptr, cnt, DHP);

    // 5. T = relu(Z@W1+b1)
    gemm_f<0,1,256><<<dim3(1, NMO / 64), 256, SMF256>>>(
        Z, nullptr, nullptr, B1, 320, b1, nullptr, nullptr, T, nullptr, DEM);

    // 6. out = T@W2+b2
    gemm_f<0,0,256><<<dim3(1, NMO / 64), 256, SMF256>>>(
        T, nullptr, nullptr, B2, 256, b2, nullptr, nullptr, out, nullptr, DEM);
}

// round 16
// speedup vs baseline: 1.0894x; 1.0894x over previous
#include <cuda_runtime.h>
#include <cuda_fp16.h>
#include <cstdint>
#include <cstddef>

#define NAT 131072
#define NBO 262144
#define NMO 4096
#define DHP 320
#define DEM 256

// ---------------- scratch (device globals; no allocation) ----------------
__device__ __align__(16) __half g_H0[(size_t)NBO * DHP];
__device__ __align__(16) __half g_Hb[(size_t)NBO * DHP];
__device__ __align__(16) __half g_Mv1[(size_t)NAT * DHP];
__device__ __align__(16) __half g_Mv2[(size_t)NAT * DHP];
__device__ float g_Z [(size_t)NMO * DHP];
__device__ float g_cnt[NMO];
__device__ float g_T [(size_t)NMO * DEM];
__device__ float g_bo[DHP];
__device__ __align__(16) __half g_Bh0[320 * 96];
__device__ __align__(16) __half g_Bh [320 * 320];
__device__ __align__(16) __half g_Bo [320 * 384];
__device__ __align__(16) __half g_B1 [256 * 320];
__device__ __align__(16) __half g_B2 [256 * 256];

// ---------------- PTX helpers ----------------
__device__ __forceinline__ uint32_t smem_u32(const void* p) {
    uint32_t a;
    asm("{ .reg .u64 t; cvta.to.shared.u64 t, %1; cvt.u32.u64 %0, t; }"
        : "=r"(a) : "l"(p));
    return a;
}
__device__ __forceinline__ void cpa16(uint32_t dst, const void* src) {
    asm volatile("cp.async.cg.shared.global [%0], [%1], 16;"
                 :: "r"(dst), "l"(src) : "memory");
}
__device__ __forceinline__ void cp_commit() {
    asm volatile("cp.async.commit_group;" ::: "memory");
}
template<int N>
__device__ __forceinline__ void cp_wait() {
    asm volatile("cp.async.wait_group %0;" :: "n"(N) : "memory");
}
__device__ __forceinline__ void ldsm4(uint32_t* r, uint32_t a) {
    asm volatile("ldmatrix.sync.aligned.m8n8.x4.shared.b16 {%0,%1,%2,%3}, [%4];"
                 : "=r"(r[0]), "=r"(r[1]), "=r"(r[2]), "=r"(r[3]) : "r"(a));
}
__device__ __forceinline__ void mma16816(float* c, const uint32_t* a, const uint32_t* b) {
    asm volatile(
        "mma.sync.aligned.m16n8k16.row.col.f32.f16.f16.f32 "
        "{%0,%1,%2,%3}, {%4,%5,%6,%7}, {%8,%9}, {%0,%1,%2,%3};"
        : "+f"(c[0]), "+f"(c[1]), "+f"(c[2]), "+f"(c[3])
        : "r"(a[0]), "r"(a[1]), "r"(a[2]), "r"(a[3]), "r"(b[0]), "r"(b[1]));
}
__device__ __forceinline__ void sts16(uint32_t a, uint32_t x, uint32_t y,
                                      uint32_t z, uint32_t w) {
    asm volatile("st.shared.v4.b32 [%0], {%1,%2,%3,%4};"
                 :: "r"(a), "r"(x), "r"(y), "r"(z), "r"(w) : "memory");
}
__device__ __forceinline__ void red2f(float* addr, float x, float y) {
    asm volatile("red.global.add.v2.f32 [%0], {%1,%2};"
                 :: "l"(addr), "f"(x), "f"(y) : "memory");
}
__device__ __forceinline__ void red2h(__half* addr, float x, float y) {
    __half2 h = __floats2half2_rn(x, y);
    asm volatile("red.global.add.noftz.f16x2 [%0], %1;"
                 :: "l"(addr), "r"(*(uint32_t*)&h) : "memory");
}

// ---------------- weight prep (transpose + fp16 round) ----------------
__global__ void prep_bt_k(const float* __restrict__ W, __half* __restrict__ out,
                          int Ksrc, int Nsrc, int KP, int Nrows) {
    int idx = blockIdx.x * 256 + threadIdx.x;
    if (idx >= Nrows * KP) return;
    int n = idx / KP, k = idx - n * KP;
    float v = (k < Ksrc && n < Nsrc) ? W[(size_t)k * Nsrc + n] : 0.f;
    out[(size_t)n * KP + k] = __float2half_rn(v);
}

__global__ void pad_k(const float* __restrict__ in, float* __restrict__ out,
                      int IC, int OC) {
    int idx = blockIdx.x * blockDim.x + threadIdx.x;
    if (idx >= OC) return;
    out[idx] = (idx < IC) ? in[idx] : 0.f;
}

__global__ void count_k(const int* __restrict__ batch, float* __restrict__ cnt) {
    int a = blockIdx.x * blockDim.x + threadIdx.x;
    if (a < NAT) atomicAdd(&cnt[batch[a]], 1.f);
}

// ---------------- fused GEMM (BM=64, BN=N, fp16, 2-stage, 1 barrier) ------
// AMODE: 0 plain(f32) ; 1 h0 concat-gather(V,E f32) ;
//        2 message: Mv(f16)[g[r]] - H(f16)[(r^1)] ;
//        5 message+relu: Mv(f16) - relu(H(f16)[(r^1)]) ;
//        3 wo concat: V(f32) | Mv(f16)
// EPI:   0 C=acc+aux_f[c] (f32) ; 1 C=relu(acc+aux_f[c]) (f32) ;
//        2 v=relu(acc+aux_h[r*N+c]); C(f16)=v; scatter f16 ;
//        3 C(f16)=acc; scatter relu(acc) f16 ;
//        4 v=relu(acc+aux_h[r*N+c]); scatter f16 only ;
//        5 v=relu(acc+aux_f[c])/cnt[sidx[r]]; scatter f32 only (cnt via C2)
template<int AMODE>
__device__ __forceinline__ void loadA8(const void* __restrict__ A1v,
                                       const void* __restrict__ A2v,
                                       long long row, int s, int k0,
                                       int KP, float* va) {
    if (AMODE == 0) {
        const float4* p = (const float4*)((const float*)A1v + row * KP + k0);
        float4 a = p[0], b = p[1];
        va[0]=a.x; va[1]=a.y; va[2]=a.z; va[3]=a.w;
        va[4]=b.x; va[5]=b.y; va[6]=b.z; va[7]=b.w;
    } else if (AMODE == 2 || AMODE == 5) {
        const uint4 mv = *(const uint4*)((const __half*)A1v + (size_t)s * DHP + k0);
        const uint4 hv = *(const uint4*)((const __half*)A2v +
                                         (size_t)(row ^ 1) * DHP + k0);
        const __half2* mp = (const __half2*)&mv;
        const __half2* hp = (const __half2*)&hv;
#pragma unroll
        for (int i = 0; i < 4; i++) {
            float2 m = __half22float2(mp[i]);
            float2 h = __half22float2(hp[i]);
            if (AMODE == 5) { h.x = fmaxf(h.x, 0.f); h.y = fmaxf(h.y, 0.f); }
            va[2*i]   = m.x - h.x;
            va[2*i+1] = m.y - h.y;
        }
    } else if (AMODE == 1) {
        const float* A1 = (const float*)A1v;
        const float* A2 = (const float*)A2v;
#pragma unroll
        for (int j = 0; j < 8; j++) {
            int k = k0 + j;
            va[j] = (k < 72) ? A1[(size_t)s * 72 + k]
                             : (k < 86 ? A2[row * 14 + (k - 72)] : 0.f);
        }
    } else { // AMODE 3
        const float* A1 = (const float*)A1v;
        const __half* A2 = (const __half*)A2v;
#pragma unroll
        for (int j = 0; j < 8; j++) {
            int k = k0 + j;
            va[j] = (k < 72) ? A1[row * 72 + k]
                             : (k < 372 ? __half2float(A2[row * DHP + (k - 72)])
                                        : 0.f);
        }
    }
}

__device__ __forceinline__ void storeA8(uint32_t ahi, const float* va) {
    uint32_t h[4];
#pragma unroll
    for (int j = 0; j < 4; j++) {
        __half2 hp;
        hp.x = __float2half_rn(va[2*j]);
        hp.y = __float2half_rn(va[2*j+1]);
        h[j] = *(uint32_t*)&hp;
    }
    sts16(ahi, h[0], h[1], h[2], h[3]);
}

template<int AMODE, int EPI, int BN>
__global__ void __launch_bounds__(256, 2)
gemm_f(const void* __restrict__ A1v, const void* __restrict__ A2v,
       const int* __restrict__ gidx,
       const __half* __restrict__ Bt, int KP,
       const void* __restrict__ auxv,
       const int* __restrict__ sidx, void* __restrict__ Sv,
       void* __restrict__ Cv, const float* __restrict__ C2, int N) {
    constexpr int NT = BN / 32;                 // n-tiles (8 cols) per warp
    constexpr int RS = 80;
    constexpr int ABUF = 64 * RS;
    constexpr int BBUF = BN * RS;
    constexpr int STG = ABUF + BBUF;            // [Ahi][Bhi]
    extern __shared__ __align__(16) char sm[];
    const uint32_t sbase = smem_u32(sm);

    const int tid = threadIdx.x;
    const int wid = tid >> 5, lane = tid & 31;
    const int wm = wid & 1, wn = wid >> 1;
    const long long bm = (long long)blockIdx.y * 64;
    const int nW = KP >> 5;

    const int arow = tid >> 2;                  // 0..63
    const int kh = (tid & 3) * 8;               // 0,8,16,24
    const long long grow = bm + arow;
    const int s = (AMODE == 1 || AMODE == 2 || AMODE == 5) ? gidx[grow] : 0;

    float acc[2][NT][4];
#pragma unroll
    for (int i = 0; i < 2; i++)
#pragma unroll
        for (int j = 0; j < NT; j++)
#pragma unroll
            for (int t = 0; t < 4; t++) acc[i][j][t] = 0.f;

    const int aRow = (lane & 7) + ((lane >> 3) & 1) * 8;
    const int aK   = (lane >> 4) * 8;
    const int bRow4 = (lane & 7) + ((lane >> 4) << 3);
    const int bK4   = ((lane >> 3) & 1) * 8;

    auto loadB = [&](int w, int buf) {
        const uint32_t bhi = sbase + buf * STG + ABUF;
        for (int idx = tid; idx < BN * 4; idx += 256) {
            int row = idx >> 2, sg = idx & 3;
            cpa16(bhi + row * RS + sg * 16,
                  Bt + (size_t)row * KP + w * 32 + sg * 8);
        }
    };

    // prologue: window 0
    {
        float va[8];
        loadA8<AMODE>(A1v, A2v, grow, s, kh, KP, va);
        storeA8(sbase + arow * RS + kh * 2, va);
        loadB(0, 0);
        cp_commit();
    }

    for (int w = 0; w < nW; ++w) {
        const int buf = w & 1;
        const bool more = (w + 1 < nW);
        float va[8];
        if (more) {
            loadA8<AMODE>(A1v, A2v, grow, s, (w + 1) * 32 + kh, KP, va);
            loadB(w + 1, buf ^ 1);
            cp_commit();
        }
        if (more) cp_wait<1>(); else cp_wait<0>();
        __syncthreads();                        // single barrier per window
        const uint32_t as = sbase + buf * STG;
        const uint32_t bs = as + ABUF;
#pragma unroll
        for (int ks = 0; ks < 32; ks += 16) {
            uint32_t afh[2][4];
#pragma unroll
            for (int mt = 0; mt < 2; ++mt) {
                uint32_t ar = as + (wm * 32 + mt * 16 + aRow) * RS + (ks + aK) * 2;
                ldsm4(afh[mt], ar);
            }
#pragma unroll
            for (int ntp = 0; ntp < NT / 2; ++ntp) {
                uint32_t bh4[4];
                uint32_t br = bs + (wn * NT * 8 + ntp * 16 + bRow4) * RS + (ks + bK4) * 2;
                ldsm4(bh4, br);
#pragma unroll
                for (int mt = 0; mt < 2; ++mt)
#pragma unroll
                    for (int h = 0; h < 2; ++h)
                        mma16816(acc[mt][ntp*2 + h], afh[mt], bh4 + h*2);
            }
        }
        // store next-A into buf^1 after own MMA; lagging warps only read buf.
        // visibility for window w+1 is provided by its top barrier.
        if (more) {
            storeA8(sbase + (buf ^ 1) * STG + arow * RS + kh * 2, va);
        }
    }

    // ---- epilogue ----
    const __half* auxh = (const __half*)auxv;
    const float*  auxf = (const float*)auxv;
    __half* Ch = (__half*)Cv;
    float*  Cf = (float*)Cv;
    __half* Sh = (__half*)Sv;
    float*  Sf = (float*)Sv;
    const int gid = lane >> 2, tig = lane & 3;
#pragma unroll
    for (int mt = 0; mt < 2; ++mt) {
        const long long r0 = bm + wm * 32 + mt * 16 + gid;
        const long long r1 = r0 + 8;
        int si0 = 0, si1 = 0;
        float inv0 = 1.f, inv1 = 1.f;
        if (EPI >= 2) { si0 = sidx[r0]; si1 = sidx[r1]; }
        if (EPI == 5) {
            inv0 = 1.f / fmaxf(C2[si0], 1.f);
            inv1 = 1.f / fmaxf(C2[si1], 1.f);
        }
#pragma unroll
        for (int nt = 0; nt < NT; ++nt) {
            const int c0 = wn * NT * 8 + nt * 8 + tig * 2;
            float v00 = acc[mt][nt][0], v01 = acc[mt][nt][1];
            float v10 = acc[mt][nt][2], v11 = acc[mt][nt][3];
            float r00, r01, r10, r11;
            if (EPI == 0 || EPI == 1 || EPI == 5) {
                float2 ax = *(const float2*)(auxf + c0);
                r00 = v00 + ax.x; r01 = v01 + ax.y;
                r10 = v10 + ax.x; r11 = v11 + ax.y;
            } else if (EPI == 2 || EPI == 4) {
                float2 a0 = __half22float2(*(const __half2*)(auxh + r0 * N + c0));
                float2 a1 = __half22float2(*(const __half2*)(auxh + r1 * N + c0));
                r00 = v00 + a0.x; r01 = v01 + a0.y;
                r10 = v10 + a1.x; r11 = v11 + a1.y;
            } else { // EPI==3
                r00 = v00; r01 = v01; r10 = v10; r11 = v11;
            }
            if (EPI != 0) {
                r00 = fmaxf(r00, 0.f); r01 = fmaxf(r01, 0.f);
                r10 = fmaxf(r10, 0.f); r11 = fmaxf(r11, 0.f);
            }
            if (EPI == 5) {
                r00 *= inv0; r01 *= inv0; r10 *= inv1; r11 *= inv1;
            }
            if (EPI == 0 || EPI == 1) {
                *(float2*)(Cf + r0 * N + c0) = make_float2(r00, r01);
                *(float2*)(Cf + r1 * N + c0) = make_float2(r10, r11);
            } else if (EPI == 2) {
                *(__half2*)(Ch + r0 * N + c0) = __floats2half2_rn(r00, r01);
                *(__half2*)(Ch + r1 * N + c0) = __floats2half2_rn(r10, r11);
            } else if (EPI == 3) {
                *(__half2*)(Ch + r0 * N + c0) = __floats2half2_rn(v00, v01);
                *(__half2*)(Ch + r1 * N + c0) = __floats2half2_rn(v10, v11);
            }
            if (EPI == 5) {
                float* s0 = Sf + (size_t)si0 * DHP + c0;
                float* s1 = Sf + (size_t)si1 * DHP + c0;
                if (r00 != 0.f || r01 != 0.f) red2f(s0, r00, r01);
                if (r10 != 0.f || r11 != 0.f) red2f(s1, r10, r11);
            } else if (EPI >= 2) {
                __half* s0 = Sh + (size_t)si0 * DHP + c0;
                __half* s1 = Sh + (size_t)si1 * DHP + c0;
                if (r00 != 0.f || r01 != 0.f) red2h(s0, r00, r01);
                if (r10 != 0.f || r11 != 0.f) red2h(s1, r10, r11);
            }
        }
    }
}

// ---------------- launcher ----------------
extern "C" void kernel_launch(void* const* d_in, const int* in_sizes, int n_in,
                              void* d_out, int out_size) {
    const float* V    = (const float*)d_in[0];
    const float* E    = (const float*)d_in[1];
    const int*   esrc = (const int*)d_in[2];
    const int*   edst = (const int*)d_in[3];
    const int*   batc = (const int*)d_in[5];
    int wi = 6;
    if (n_in >= 15 && in_sizes[6] == 1) wi = 7;
    const float* W_i = (const float*)d_in[wi + 0];
    const float* W_h = (const float*)d_in[wi + 1];
    const float* W_o = (const float*)d_in[wi + 2];
    const float* b_o = (const float*)d_in[wi + 3];
    const float* W1  = (const float*)d_in[wi + 4];
    const float* b1  = (const float*)d_in[wi + 5];
    const float* W2  = (const float*)d_in[wi + 6];
    const float* b2  = (const float*)d_in[wi + 7];
    float* out = (float*)d_out;

    float *Z, *cnt, *T, *bo;
    __half *H0, *Hb, *Mv1, *Mv2, *Bh0, *Bh, *Bo, *B1, *B2;
    cudaGetSymbolAddress((void**)&H0,  g_H0);
    cudaGetSymbolAddress((void**)&Hb,  g_Hb);
    cudaGetSymbolAddress((void**)&Mv1, g_Mv1);
    cudaGetSymbolAddress((void**)&Mv2, g_Mv2);
    cudaGetSymbolAddress((void**)&Z,   g_Z);
    cudaGetSymbolAddress((void**)&cnt, g_cnt);
    cudaGetSymbolAddress((void**)&T,   g_T);
    cudaGetSymbolAddress((void**)&bo,  g_bo);
    cudaGetSymbolAddress((void**)&Bh0, g_Bh0);
    cudaGetSymbolAddress((void**)&Bh,  g_Bh);
    cudaGetSymbolAddress((void**)&Bo,  g_Bo);
    cudaGetSymbolAddress((void**)&B1,  g_B1);
    cudaGetSymbolAddress((void**)&B2,  g_B2);

    const int SMF320 = 2 * (64 * 80 + 320 * 80);  // 61440
    const int SMF256 = 2 * (64 * 80 + 256 * 80);  // 51200
    cudaFuncSetAttribute(gemm_f<1,3,320>, cudaFuncAttributeMaxDynamicSharedMemorySize, SMF320);
    cudaFuncSetAttribute(gemm_f<5,2,320>, cudaFuncAttributeMaxDynamicSharedMemorySize, SMF320);
    cudaFuncSetAttribute(gemm_f<2,4,320>, cudaFuncAttributeMaxDynamicSharedMemorySize, SMF320);
    cudaFuncSetAttribute(gemm_f<3,5,320>, cudaFuncAttributeMaxDynamicSharedMemorySize, SMF320);
    cudaFuncSetAttribute(gemm_f<0,1,256>, cudaFuncAttributeMaxDynamicSharedMemorySize, SMF256);
    cudaFuncSetAttribute(gemm_f<0,0,256>, cudaFuncAttributeMaxDynamicSharedMemorySize, SMF256);

    // weight prep (transpose + fp16)
    prep_bt_k<<<(320 * 96  + 255) / 256, 256>>>(W_i, Bh0, 86,  300, 96,  320);
    prep_bt_k<<<(320 * 320 + 255) / 256, 256>>>(W_h, Bh,  300, 300, 320, 320);
    prep_bt_k<<<(320 * 384 + 255) / 256, 256>>>(W_o, Bo,  372, 300, 384, 320);
    prep_bt_k<<<(256 * 320 + 255) / 256, 256>>>(W1,  B1,  300, 256, 320, 256);
    prep_bt_k<<<(256 * 256 + 255) / 256, 256>>>(W2,  B2,  256, 256, 256, 256);
    pad_k<<<2, 256>>>(b_o, bo, 300, DHP);

    const size_t MVB = (size_t)NAT * DHP * sizeof(__half);
    cudaMemsetAsync(cnt, 0, (size_t)NMO * sizeof(float));
    count_k<<<(NAT + 255) / 256, 256>>>(batc, cnt);
    cudaMemsetAsync(Mv1, 0, MVB);
    cudaMemsetAsync(Mv2, 0, MVB);
    cudaMemsetAsync(Z, 0, (size_t)NMO * DHP * sizeof(float));

    // 1. H0(f16) = concat(V[src],E)@W_i (pre-relu) ; scatter relu -> Mv1(f16)
    gemm_f<1,3,320><<<dim3(1, NBO / 64), 256, SMF320>>>(
        V, E, esrc, Bh0, 96, nullptr, edst, Mv1, H0, nullptr, DHP);

    // 2. iter1: Hb(f16) = relu(H0 + (Mv1[src]-relu(H0)[rev])@Wh) ; scatter -> Mv2
    gemm_f<5,2,320><<<dim3(1, NBO / 64), 256, SMF320>>>(
        Mv1, H0, esrc, Bh, 320, H0, edst, Mv2, Hb, nullptr, DHP);

    // 3. iter2: relu(H0 + (Mv2[src]-Hb[rev])@Wh) scattered -> Mv1 (no store)
    cudaMemsetAsync(Mv1, 0, MVB);
    gemm_f<2,4,320><<<dim3(1, NBO / 64), 256, SMF320>>>(
        Mv2, Hb, esrc, Bh, 320, H0, edst, Mv1, nullptr, nullptr, DHP);

    // 4. relu(concat(V,Mv1)@Wo + bo) / cnt pooled -> Z(f32) (mean fused)
    gemm_f<3,5,320><<<dim3(1, NAT / 64), 256, SMF320>>>(
        V, Mv1, nullptr, Bo, 384, bo, batc, Z, nullptr, cnt, DHP);

    // 5. T = relu(Z@W1+b1)
    gemm_f<0,1,256><<<dim3(1, NMO / 64), 256, SMF256>>>(
        Z, nullptr, nullptr, B1, 320, b1, nullptr, nullptr, T, nullptr, DEM);

    // 6. out = T@W2+b2
    gemm_f<0,0,256><<<dim3(1, NMO / 64), 256, SMF256>>>(
        T, nullptr, nullptr, B2, 256, b2, nullptr, nullptr, out, nullptr, DEM);
}